// round 4
// baseline (speedup 1.0000x reference)
#include <cuda_runtime.h>

#define LL 4096
#define CC 16
#define NB 16
#define OC 64
#define KS 7

typedef unsigned long long u64;

__device__ __forceinline__ u64 pack2(float lo, float hi) {
    u64 r;
    asm("mov.b64 %0, {%1, %2};" : "=l"(r) : "f"(lo), "f"(hi));
    return r;
}
__device__ __forceinline__ u64 ffma2(u64 a, u64 b, u64 c) {
    u64 d;
    asm("fma.rn.f32x2 %0, %1, %2, %3;" : "=l"(d) : "l"(a), "l"(b), "l"(c));
    return d;
}
__device__ __forceinline__ float2 unpack2(u64 v) {
    float lo, hi;
    asm("mov.b64 {%0, %1}, %2;" : "=f"(lo), "=f"(hi) : "l"(v));
    return make_float2(lo, hi);
}

__global__ __launch_bounds__(256, 5) void deform_conv_kernel(
    const float* __restrict__ x,
    const float* __restrict__ pw, const float* __restrict__ pb,
    const float* __restrict__ mw, const float* __restrict__ mb,
    const float* __restrict__ cw, const float* __restrict__ cb,
    float* __restrict__ out)
{
    // conv weights duplicated into both f32x2 lanes, padded 7->8 for LDS.128
    __shared__ u64 s_cw2[OC][8];
    __shared__ u64 s_cb2[OC];
    __shared__ float s_pw[KS * 3], s_pb[KS], s_mw[KS * 3], s_mb[KS];

    const int tid = threadIdx.x;
    for (int i = tid; i < OC * 8; i += blockDim.x) {
        const int oc = i >> 3, k = i & 7;
        const float w = (k < KS) ? cw[oc * KS + k] : 0.f;
        s_cw2[oc][k] = pack2(w, w);
    }
    if (tid < OC) { const float bv = cb[tid]; s_cb2[tid] = pack2(bv, bv); }
    if (tid < KS * 3) { s_pw[tid] = pw[tid]; s_mw[tid] = mw[tid]; }
    if (tid < KS)     { s_pb[tid] = pb[tid]; s_mb[tid] = mb[tid]; }
    __syncthreads();

    const int t  = blockIdx.x * blockDim.x + tid;   // 2^19 threads total
    const int c2 = t & 7;                           // channel pair (2 floats)
    const int l  = (t >> 3) & (LL - 1);
    const int b  = t >> 15;                         // 8*LL = 2^15 per batch

    const float* xb = x + (size_t)b * (LL * CC);
    const float2* xb2 = (const float2*)xb;

    // 3-tap window over 2 channels (zero padding at the edges, pad=1 conv)
    float2 sm1 = (l > 0)      ? xb2[(l - 1) * 8 + c2] : make_float2(0.f, 0.f);
    float2 s0  =                xb2[l * 8 + c2];
    float2 sp1 = (l < LL - 1) ? xb2[(l + 1) * 8 + c2] : make_float2(0.f, 0.f);

    float win[2][3] = {{sm1.x, s0.x, sp1.x}, {sm1.y, s0.y, sp1.y}};

    u64 vv[KS];   // packed (v_ch0, v_ch1) per kernel tap
    #pragma unroll
    for (int k = 0; k < KS; ++k) {
        const float w0 = s_pw[k * 3], w1 = s_pw[k * 3 + 1], w2 = s_pw[k * 3 + 2];
        const float u0 = s_mw[k * 3], u1 = s_mw[k * 3 + 1], u2 = s_mw[k * 3 + 2];
        const float bo = s_pb[k], bm = s_mb[k];
        const float pbase = (float)(l + 1 + (k - 3));   // p_0 is 1-indexed
        float vk[2];
        #pragma unroll
        for (int i = 0; i < 2; ++i) {
            float off = fmaf(w2, win[i][2], fmaf(w1, win[i][1], fmaf(w0, win[i][0], bo)));
            float z   = fmaf(u2, win[i][2], fmaf(u1, win[i][1], fmaf(u0, win[i][0], bm)));
            float m   = 1.f / (1.f + __expf(-z));       // sigmoid
            float p   = pbase + off;
            float qlt = fminf(fmaxf(floorf(p), 0.f), (float)(LL - 1));
            float qrb = fminf(qlt + 1.f, (float)(LL - 1));
            float pc  = fminf(fmaxf(p, 0.f), (float)(LL - 1));
            float glt = 1.f + (qlt - pc);
            float grb = 1.f - (qrb - pc);
            const int ch = c2 * 2 + i;
            float xlt = xb[(int)qlt * CC + ch];
            float xrb = xb[(int)qrb * CC + ch];
            vk[i] = (glt * xlt + grb * xrb) * m;
        }
        vv[k] = pack2(vk[0], vk[1]);
    }

    const ulonglong2* scw2 = (const ulonglong2*)s_cw2;  // [64][4] 16B rows
    float2* out2 = (float2*)out;
    const int obase = ((b * OC) * LL + l) * 8 + c2;     // float2 index

    #pragma unroll 8
    for (int oc = 0; oc < OC; ++oc) {
        ulonglong2 w01 = scw2[oc * 4 + 0];              // taps 0,1
        ulonglong2 w23 = scw2[oc * 4 + 1];              // taps 2,3
        ulonglong2 w45 = scw2[oc * 4 + 2];              // taps 4,5
        ulonglong2 w67 = scw2[oc * 4 + 3];              // tap  6 (+pad)
        u64 acc = s_cb2[oc];
        acc = ffma2(vv[0], w01.x, acc);
        acc = ffma2(vv[1], w01.y, acc);
        acc = ffma2(vv[2], w23.x, acc);
        acc = ffma2(vv[3], w23.y, acc);
        acc = ffma2(vv[4], w45.x, acc);
        acc = ffma2(vv[5], w45.y, acc);
        acc = ffma2(vv[6], w67.x, acc);
        __stcs(&out2[obase + oc * (LL * 8)], unpack2(acc));
    }
}

extern "C" void kernel_launch(void* const* d_in, const int* in_sizes, int n_in,
                              void* d_out, int out_size)
{
    const float* x  = (const float*)d_in[0];
    const float* pw = (const float*)d_in[1];
    const float* pb = (const float*)d_in[2];
    const float* mw = (const float*)d_in[3];
    const float* mb = (const float*)d_in[4];
    const float* cw = (const float*)d_in[5];
    const float* cb = (const float*)d_in[6];
    float* out = (float*)d_out;

    // 16 batches * 4096 positions * 8 channel-pairs = 524288 threads
    deform_conv_kernel<<<2048, 256>>>(x, pw, pb, mw, mb, cw, cb, out);
}

// round 5
// speedup vs baseline: 1.1942x; 1.1942x over previous
#include <cuda_runtime.h>

#define LL 4096
#define CC 16
#define NB 16
#define OC 64
#define KS 7

typedef unsigned long long u64;

__device__ __forceinline__ u64 pack2(float lo, float hi) {
    u64 r;
    asm("mov.b64 %0, {%1, %2};" : "=l"(r) : "f"(lo), "f"(hi));
    return r;
}
__device__ __forceinline__ u64 ffma2(u64 a, u64 b, u64 c) {
    u64 d;
    asm("fma.rn.f32x2 %0, %1, %2, %3;" : "=l"(d) : "l"(a), "l"(b), "l"(c));
    return d;
}
__device__ __forceinline__ u64 fmul2(u64 a, u64 b) {
    u64 d;
    asm("mul.rn.f32x2 %0, %1, %2;" : "=l"(d) : "l"(a), "l"(b));
    return d;
}
__device__ __forceinline__ void unpack2(u64 v, float& lo, float& hi) {
    asm("mov.b64 {%0, %1}, %2;" : "=f"(lo), "=f"(hi) : "l"(v));
}

__global__ __launch_bounds__(256, 5) void deform_conv_kernel(
    const float* __restrict__ x,
    const float* __restrict__ pw, const float* __restrict__ pb,
    const float* __restrict__ mw, const float* __restrict__ mb,
    const float* __restrict__ cw, const float* __restrict__ cb,
    float* __restrict__ out)
{
    // conv weights: [oc][8] scalar floats, taps 0-6 + bias in slot 7.
    // Read in epilogue as u64 pairs: (w0,w1)(w2,w3)(w4,w5)(w6,bias).
    __shared__ float s_w8[OC][8];
    // prep conv weights, lane-duplicated (tiny, read once per tap not per oc)
    __shared__ u64 s_pwd[KS * 3], s_pbd[KS], s_mwd[KS * 3], s_mbd[KS];

    const int tid = threadIdx.x;
    for (int i = tid; i < OC * 8; i += blockDim.x) {
        const int oc = i >> 3, k = i & 7;
        s_w8[oc][k] = (k < KS) ? cw[oc * KS + k] : cb[oc];
    }
    if (tid < KS * 3) {
        const float a = pw[tid], c = mw[tid];
        s_pwd[tid] = pack2(a, a);
        s_mwd[tid] = pack2(c, c);
    }
    if (tid < KS) {
        const float a = pb[tid], c = mb[tid];
        s_pbd[tid] = pack2(a, a);
        s_mbd[tid] = pack2(c, c);
    }
    __syncthreads();

    const int t  = blockIdx.x * blockDim.x + tid;   // 2^19 threads total
    const int c2 = t & 7;                           // channel pair (2 floats)
    const int l  = (t >> 3) & (LL - 1);
    const int b  = t >> 15;                         // 8*LL = 2^15 per batch

    const float* xb = x + (size_t)b * (LL * CC);
    const float2* xb2 = (const float2*)xb;

    // 3-tap window over 2 channels (zero padding at the edges, pad=1 conv)
    float2 sm1 = (l > 0)      ? xb2[(l - 1) * 8 + c2] : make_float2(0.f, 0.f);
    float2 s0  =                xb2[l * 8 + c2];
    float2 sp1 = (l < LL - 1) ? xb2[(l + 1) * 8 + c2] : make_float2(0.f, 0.f);

    // channel-paired window values for f32x2 prep convs
    const u64 winp0 = pack2(sm1.x, sm1.y);
    const u64 winp1 = pack2(s0.x,  s0.y);
    const u64 winp2 = pack2(sp1.x, sp1.y);

    float vk[2][KS];
    #pragma unroll
    for (int k = 0; k < KS; ++k) {
        // offset + mask convs, both channels at once
        u64 off2 = ffma2(winp2, s_pwd[k * 3 + 2],
                   ffma2(winp1, s_pwd[k * 3 + 1],
                   ffma2(winp0, s_pwd[k * 3 + 0], s_pbd[k])));
        u64 z2   = ffma2(winp2, s_mwd[k * 3 + 2],
                   ffma2(winp1, s_mwd[k * 3 + 1],
                   ffma2(winp0, s_mwd[k * 3 + 0], s_mbd[k])));
        float offc[2], zc[2];
        unpack2(off2, offc[0], offc[1]);
        unpack2(z2,   zc[0],   zc[1]);

        const float pbase = (float)(l + 1 + (k - 3));   // p_0 is 1-indexed
        #pragma unroll
        for (int i = 0; i < 2; ++i) {
            float m   = __fdividef(1.f, 1.f + __expf(-zc[i]));  // sigmoid
            float p   = pbase + offc[i];
            float qlt = fminf(fmaxf(floorf(p), 0.f), (float)(LL - 1));
            float qrb = fminf(qlt + 1.f, (float)(LL - 1));
            float pc  = fminf(fmaxf(p, 0.f), (float)(LL - 1));
            float glt = 1.f + (qlt - pc);
            float grb = 1.f - (qrb - pc);
            const int ch = c2 * 2 + i;
            float xlt = xb[(int)qlt * CC + ch];
            float xrb = xb[(int)qrb * CC + ch];
            vk[i][k] = (glt * xlt + grb * xrb) * m;
        }
    }

    // tap-paired packed v values (natural pairs, no duplication)
    u64 v01[2], v23[2], v45[2], v6b[2];
    #pragma unroll
    for (int i = 0; i < 2; ++i) {
        v01[i] = pack2(vk[i][0], vk[i][1]);
        v23[i] = pack2(vk[i][2], vk[i][3]);
        v45[i] = pack2(vk[i][4], vk[i][5]);
        v6b[i] = pack2(vk[i][6], 1.f);          // lane1 multiplies the bias
    }

    float2* out2 = (float2*)out;
    const int obase = ((b * OC) * LL + l) * 8 + c2;     // float2 index

    #pragma unroll 4
    for (int oc = 0; oc < OC; ++oc) {
        const ulonglong2* row = (const ulonglong2*)s_w8[oc];
        ulonglong2 wa = row[0];     // (w0,w1) (w2,w3)
        ulonglong2 wb = row[1];     // (w4,w5) (w6,bias)
        float r[2];
        #pragma unroll
        for (int i = 0; i < 2; ++i) {
            u64 acc = fmul2(v6b[i], wb.y);              // (w6*v6, bias)
            acc = ffma2(v01[i], wa.x, acc);
            acc = ffma2(v23[i], wa.y, acc);
            acc = ffma2(v45[i], wb.x, acc);
            float lo, hi;
            unpack2(acc, lo, hi);
            r[i] = lo + hi;
        }
        __stcs(&out2[obase + oc * (LL * 8)], make_float2(r[0], r[1]));
    }
}

extern "C" void kernel_launch(void* const* d_in, const int* in_sizes, int n_in,
                              void* d_out, int out_size)
{
    const float* x  = (const float*)d_in[0];
    const float* pw = (const float*)d_in[1];
    const float* pb = (const float*)d_in[2];
    const float* mw = (const float*)d_in[3];
    const float* mb = (const float*)d_in[4];
    const float* cw = (const float*)d_in[5];
    const float* cb = (const float*)d_in[6];
    float* out = (float*)d_out;

    // 16 batches * 4096 positions * 8 channel-pairs = 524288 threads
    deform_conv_kernel<<<2048, 256>>>(x, pw, pb, mw, mb, cw, cb, out);
}